// round 2
// baseline (speedup 1.0000x reference)
#include <cuda_runtime.h>

// Lingunet5Filter: 5 levels of per-batch 1x1 dynamic conv (batched GEMM) + instance norm (levels 1-4).
//   Y[b] (128 x N) = F[b] (128 x 128) @ X[b] (128 x N),  N = s^2, s in {128,64,32,16,8}, B=32
//   levels 1-4: y = (y - mean_spatial) / sqrt(var_spatial + 1e-5)
//
// Kernel 1: all 5 levels as one batched-GEMM launch (BM=128=M, BN=128, BK=16, 256 thr,
//           8x8 micro-tile computed with packed fma.rn.f32x2). Emits per-(b,o,tile)
//           partial sum / sumsq for the norm (deterministic, no atomics).
// Kernel 2: per-(b,o) row: reduce partials -> mean/rstd, normalize in place (levels 0-3).

#define EPSN 1e-5f

__constant__ int       c_N[5]    = {16384, 4096, 1024, 256, 64};
__constant__ int       c_nT[5]   = {128, 32, 8, 2, 1};
__constant__ long long c_yoff[5] = {0LL, 67108864LL, 83886080LL, 88080384LL, 89128960LL};
__constant__ long long c_poff[4] = {0LL, 524288LL, 655360LL, 688128LL};

// partial stats scratch: levels 0-3, total 696320 entries each
__device__ float g_psum[696320];
__device__ float g_psq [696320];

// ---------------- packed f32x2 helpers ----------------
static __device__ __forceinline__ unsigned long long dup2(float a) {
    unsigned long long r;
    asm("mov.b64 %0, {%1, %1};" : "=l"(r) : "f"(a));
    return r;
}
static __device__ __forceinline__ unsigned long long pack2(float lo, float hi) {
    unsigned long long r;
    asm("mov.b64 %0, {%1, %2};" : "=l"(r) : "f"(lo), "f"(hi));
    return r;
}
static __device__ __forceinline__ void ffma2(unsigned long long& d,
                                             unsigned long long a,
                                             unsigned long long b) {
    asm("fma.rn.f32x2 %0, %1, %2, %0;" : "+l"(d) : "l"(a), "l"(b));
}
static __device__ __forceinline__ float2 unpack2(unsigned long long v) {
    float lo, hi;
    asm("mov.b64 {%0, %1}, %2;" : "=f"(lo), "=f"(hi) : "l"(v));
    return make_float2(lo, hi);
}

// ---------------- kernel 1: batched GEMM + partial stats ----------------
__global__ __launch_bounds__(256)
void lg5_gemm_kernel(const float* __restrict__ x0, const float* __restrict__ x1,
                     const float* __restrict__ x2, const float* __restrict__ x3,
                     const float* __restrict__ x4,
                     const float* __restrict__ f0, const float* __restrict__ f1,
                     const float* __restrict__ f2, const float* __restrict__ f3,
                     const float* __restrict__ f4,
                     float* __restrict__ out) {
    __shared__ float As[16][128];   // A transposed: As[k][o]
    __shared__ float Bs[16][128];   // Bs[k][n]

    const int bx = blockIdx.x;
    int L, t0;
    if (bx < 4096)      { L = 0; t0 = bx; }
    else if (bx < 5120) { L = 1; t0 = bx - 4096; }
    else if (bx < 5376) { L = 2; t0 = bx - 5120; }
    else if (bx < 5440) { L = 3; t0 = bx - 5376; }
    else                { L = 4; t0 = bx - 5440; }

    const int N    = c_N[L];
    const int nT   = c_nT[L];
    const int b    = t0 / nT;
    const int tile = t0 - b * nT;
    const int n0   = tile * 128;

    const float* X; const float* F;
    if (L == 0)      { X = x0; F = f0; }
    else if (L == 1) { X = x1; F = f1; }
    else if (L == 2) { X = x2; F = f2; }
    else if (L == 3) { X = x3; F = f3; }
    else             { X = x4; F = f4; }
    X += (size_t)b * 128 * N;
    F += (size_t)b * 128 * 128;
    float* Y = out + c_yoff[L] + (size_t)b * 128 * N;

    const int tid  = threadIdx.x;
    const int tx   = tid & 15;
    const int ty   = tid >> 4;
    const int row0 = ty * 8;
    const int col0 = tx * 8;

    // A tile load mapping: 128 rows x 16 cols = 512 float4; 2 per thread
    const int aRow0 = tid >> 2;         // 0..63  (second: +64)
    const int aC0   = (tid & 3) * 4;    // 0,4,8,12
    // B tile load mapping: 16 rows x 128 cols = 512 float4; 2 per thread
    const int bR0   = tid >> 5;         // 0..7   (second: +8)
    const int bC0   = (tid & 31) * 4;   // 0..124
    const int nb    = n0 + bC0;
    const bool bValid = (nb < N);       // N is a multiple of 64, nb multiple of 4

    unsigned long long acc[8][4];
#pragma unroll
    for (int i = 0; i < 8; i++)
#pragma unroll
        for (int j = 0; j < 4; j++) acc[i][j] = 0ULL;

    const float4 z4 = make_float4(0.f, 0.f, 0.f, 0.f);
    float4 ra0, ra1, rb0, rb1;

    // prefetch chunk 0
    ra0 = *(const float4*)&F[aRow0 * 128 + aC0];
    ra1 = *(const float4*)&F[(aRow0 + 64) * 128 + aC0];
    rb0 = bValid ? *(const float4*)&X[(size_t)bR0 * N + nb] : z4;
    rb1 = bValid ? *(const float4*)&X[(size_t)(bR0 + 8) * N + nb] : z4;

    for (int kc = 0; kc < 128; kc += 16) {
        // commit prefetched tile to smem
        As[aC0 + 0][aRow0] = ra0.x; As[aC0 + 1][aRow0] = ra0.y;
        As[aC0 + 2][aRow0] = ra0.z; As[aC0 + 3][aRow0] = ra0.w;
        As[aC0 + 0][aRow0 + 64] = ra1.x; As[aC0 + 1][aRow0 + 64] = ra1.y;
        As[aC0 + 2][aRow0 + 64] = ra1.z; As[aC0 + 3][aRow0 + 64] = ra1.w;
        *(float4*)&Bs[bR0][bC0]     = rb0;
        *(float4*)&Bs[bR0 + 8][bC0] = rb1;
        __syncthreads();

        if (kc + 16 < 128) {
            const int kn = kc + 16;
            ra0 = *(const float4*)&F[aRow0 * 128 + kn + aC0];
            ra1 = *(const float4*)&F[(aRow0 + 64) * 128 + kn + aC0];
            rb0 = bValid ? *(const float4*)&X[(size_t)(kn + bR0) * N + nb] : z4;
            rb1 = bValid ? *(const float4*)&X[(size_t)(kn + bR0 + 8) * N + nb] : z4;
        }

#pragma unroll
        for (int k = 0; k < 16; k++) {
            float4 a0 = *(const float4*)&As[k][row0];
            float4 a1 = *(const float4*)&As[k][row0 + 4];
            float4 b0 = *(const float4*)&Bs[k][col0];
            float4 b1 = *(const float4*)&Bs[k][col0 + 4];
            unsigned long long A8[8] = {dup2(a0.x), dup2(a0.y), dup2(a0.z), dup2(a0.w),
                                        dup2(a1.x), dup2(a1.y), dup2(a1.z), dup2(a1.w)};
            unsigned long long B4[4] = {pack2(b0.x, b0.y), pack2(b0.z, b0.w),
                                        pack2(b1.x, b1.y), pack2(b1.z, b1.w)};
#pragma unroll
            for (int i = 0; i < 8; i++)
#pragma unroll
                for (int j = 0; j < 4; j++)
                    ffma2(acc[i][j], A8[i], B4[j]);
        }
        __syncthreads();
    }

    // epilogue: store Y + per-row partial stats for this n-tile
    const bool cValid = (n0 + col0) < N;  // whole 8-col group valid or not (N mult of 64)
#pragma unroll
    for (int i = 0; i < 8; i++) {
        const int o = row0 + i;
        float y[8];
#pragma unroll
        for (int j = 0; j < 4; j++) {
            float2 p = unpack2(acc[i][j]);
            y[2 * j] = p.x; y[2 * j + 1] = p.y;
        }
        if (cValid) {
            *(float4*)&Y[(size_t)o * N + n0 + col0]     = make_float4(y[0], y[1], y[2], y[3]);
            *(float4*)&Y[(size_t)o * N + n0 + col0 + 4] = make_float4(y[4], y[5], y[6], y[7]);
        }
        // invalid columns had zero-filled B -> y == 0, contributes nothing to sums
        float s1 = 0.f, s2 = 0.f;
#pragma unroll
        for (int j = 0; j < 8; j++) { s1 += y[j]; s2 += y[j] * y[j]; }
        // reduce across the 16 threads (same ty) holding this row's columns
#pragma unroll
        for (int d = 8; d >= 1; d >>= 1) {
            s1 += __shfl_xor_sync(0xffffffffu, s1, d);
            s2 += __shfl_xor_sync(0xffffffffu, s2, d);
        }
        if (L < 4 && tx == 0) {
            const size_t pidx = (size_t)c_poff[L] + (size_t)(b * 128 + o) * nT + tile;
            g_psum[pidx] = s1;
            g_psq [pidx] = s2;
        }
    }
}

// ---------------- kernel 2: finalize stats + normalize (levels 0-3) ----------------
__global__ __launch_bounds__(256)
void lg5_norm_kernel(float* __restrict__ out) {
    const int L  = blockIdx.y;        // 0..3
    const int bo = blockIdx.x;        // 0..4095 == b*128 + o
    const int N  = c_N[L];
    const int nT = c_nT[L];

    float* row = out + c_yoff[L] + (size_t)bo * N;
    const float* p1 = g_psum + c_poff[L] + (size_t)bo * nT;
    const float* p2 = g_psq  + c_poff[L] + (size_t)bo * nT;

    float s1 = 0.f, s2 = 0.f;
    for (int i = threadIdx.x; i < nT; i += blockDim.x) { s1 += p1[i]; s2 += p2[i]; }
#pragma unroll
    for (int d = 16; d >= 1; d >>= 1) {
        s1 += __shfl_xor_sync(0xffffffffu, s1, d);
        s2 += __shfl_xor_sync(0xffffffffu, s2, d);
    }
    __shared__ float sh1[8], sh2[8];
    __shared__ float stats[2];
    const int w = threadIdx.x >> 5, lane = threadIdx.x & 31;
    if (lane == 0) { sh1[w] = s1; sh2[w] = s2; }
    __syncthreads();
    if (threadIdx.x == 0) {
        float S1 = 0.f, S2 = 0.f;
#pragma unroll
        for (int i = 0; i < 8; i++) { S1 += sh1[i]; S2 += sh2[i]; }
        const float invN = 1.0f / (float)N;
        const float mean = S1 * invN;
        const float var  = S2 * invN - mean * mean;
        stats[0] = mean;
        stats[1] = rsqrtf(var + EPSN);
    }
    __syncthreads();
    const float mean = stats[0], rstd = stats[1];
    for (int i = threadIdx.x * 4; i < N; i += blockDim.x * 4) {
        float4 v = *(const float4*)&row[i];
        v.x = (v.x - mean) * rstd;
        v.y = (v.y - mean) * rstd;
        v.z = (v.z - mean) * rstd;
        v.w = (v.w - mean) * rstd;
        *(float4*)&row[i] = v;
    }
}

// ---------------- launch ----------------
extern "C" void kernel_launch(void* const* d_in, const int* in_sizes, int n_in,
                              void* d_out, int out_size) {
    // identify inputs by element count (robust to metadata ordering);
    // the five filters (all 524288 elems) are l1fs..l5fs in appearance order.
    const float* xs[5] = {0, 0, 0, 0, 0};
    const float* fs[5] = {0, 0, 0, 0, 0};
    int fc = 0;
    for (int i = 0; i < n_in; i++) {
        const float* p = (const float*)d_in[i];
        switch (in_sizes[i]) {
            case 67108864: xs[0] = p; break;  // x1: 32*128*128*128
            case 16777216: xs[1] = p; break;  // x2: 32*128*64*64
            case 4194304:  xs[2] = p; break;  // x3: 32*128*32*32
            case 1048576:  xs[3] = p; break;  // x4: 32*128*16*16
            case 262144:   xs[4] = p; break;  // x5: 32*128*8*8
            case 524288:   if (fc < 5) fs[fc++] = p; break;  // l{i}fs: 32*128*128
        }
    }
    float* out = (float*)d_out;
    lg5_gemm_kernel<<<5472, 256>>>(xs[0], xs[1], xs[2], xs[3], xs[4],
                                   fs[0], fs[1], fs[2], fs[3], fs[4], out);
    lg5_norm_kernel<<<dim3(4096, 4), 256>>>(out);
}

// round 3
// speedup vs baseline: 1.0062x; 1.0062x over previous
#include <cuda_runtime.h>

// Lingunet5Filter: 5 levels of per-batch 1x1 dynamic conv (batched GEMM) + instance norm (levels 1-4).
//   Y[b] (128 x N) = F[b] (128 x 128) @ X[b] (128 x N),  N = s^2, s in {128,64,32,16,8}, B=32
//   levels 1-4: y = (y - mean_spatial) / sqrt(var_spatial + 1e-5)
//
// Kernel 1: all 5 levels as one batched-GEMM launch (BM=128=M, BN=128, BK=16, 256 thr,
//           8x8 micro-tile computed with packed fma.rn.f32x2). Emits per-(b,o,tile)
//           partial sum / sumsq for the norm (deterministic, no atomics).
// Kernel 2: per-(b,o) row: reduce partials -> mean/rstd, normalize in place (levels 0-3).

#define EPSN 1e-5f

__constant__ int       c_N[5]    = {16384, 4096, 1024, 256, 64};
__constant__ int       c_nT[5]   = {128, 32, 8, 2, 1};
__constant__ long long c_yoff[5] = {0LL, 67108864LL, 83886080LL, 88080384LL, 89128960LL};
__constant__ long long c_poff[4] = {0LL, 524288LL, 655360LL, 688128LL};

// partial stats scratch: levels 0-3, total 696320 entries each
__device__ float g_psum[696320];
__device__ float g_psq [696320];

// ---------------- packed f32x2 helpers ----------------
static __device__ __forceinline__ unsigned long long dup2(float a) {
    unsigned long long r;
    asm("mov.b64 %0, {%1, %1};" : "=l"(r) : "f"(a));
    return r;
}
static __device__ __forceinline__ unsigned long long pack2(float lo, float hi) {
    unsigned long long r;
    asm("mov.b64 %0, {%1, %2};" : "=l"(r) : "f"(lo), "f"(hi));
    return r;
}
static __device__ __forceinline__ void ffma2(unsigned long long& d,
                                             unsigned long long a,
                                             unsigned long long b) {
    asm("fma.rn.f32x2 %0, %1, %2, %0;" : "+l"(d) : "l"(a), "l"(b));
}
static __device__ __forceinline__ float2 unpack2(unsigned long long v) {
    float lo, hi;
    asm("mov.b64 {%0, %1}, %2;" : "=f"(lo), "=f"(hi) : "l"(v));
    return make_float2(lo, hi);
}

// ---------------- kernel 1: batched GEMM + partial stats ----------------
__global__ __launch_bounds__(256)
void lg5_gemm_kernel(const float* __restrict__ x0, const float* __restrict__ x1,
                     const float* __restrict__ x2, const float* __restrict__ x3,
                     const float* __restrict__ x4,
                     const float* __restrict__ f0, const float* __restrict__ f1,
                     const float* __restrict__ f2, const float* __restrict__ f3,
                     const float* __restrict__ f4,
                     float* __restrict__ out) {
    __shared__ float As[16][128];   // A transposed: As[k][o]
    __shared__ float Bs[16][128];   // Bs[k][n]

    const int bx = blockIdx.x;
    int L, t0;
    if (bx < 4096)      { L = 0; t0 = bx; }
    else if (bx < 5120) { L = 1; t0 = bx - 4096; }
    else if (bx < 5376) { L = 2; t0 = bx - 5120; }
    else if (bx < 5440) { L = 3; t0 = bx - 5376; }
    else                { L = 4; t0 = bx - 5440; }

    const int N    = c_N[L];
    const int nT   = c_nT[L];
    const int b    = t0 / nT;
    const int tile = t0 - b * nT;
    const int n0   = tile * 128;

    const float* X; const float* F;
    if (L == 0)      { X = x0; F = f0; }
    else if (L == 1) { X = x1; F = f1; }
    else if (L == 2) { X = x2; F = f2; }
    else if (L == 3) { X = x3; F = f3; }
    else             { X = x4; F = f4; }
    X += (size_t)b * 128 * N;
    F += (size_t)b * 128 * 128;
    float* Y = out + c_yoff[L] + (size_t)b * 128 * N;

    const int tid  = threadIdx.x;
    const int tx   = tid & 15;
    const int ty   = tid >> 4;
    const int row0 = ty * 8;
    const int col0 = tx * 8;

    // A tile load mapping: 128 rows x 16 cols = 512 float4; 2 per thread
    const int aRow0 = tid >> 2;         // 0..63  (second: +64)
    const int aC0   = (tid & 3) * 4;    // 0,4,8,12
    // B tile load mapping: 16 rows x 128 cols = 512 float4; 2 per thread
    const int bR0   = tid >> 5;         // 0..7   (second: +8)
    const int bC0   = (tid & 31) * 4;   // 0..124
    const int nb    = n0 + bC0;
    const bool bValid = (nb < N);       // N is a multiple of 64, nb multiple of 4

    unsigned long long acc[8][4];
#pragma unroll
    for (int i = 0; i < 8; i++)
#pragma unroll
        for (int j = 0; j < 4; j++) acc[i][j] = 0ULL;

    const float4 z4 = make_float4(0.f, 0.f, 0.f, 0.f);
    float4 ra0, ra1, rb0, rb1;

    // prefetch chunk 0
    ra0 = *(const float4*)&F[aRow0 * 128 + aC0];
    ra1 = *(const float4*)&F[(aRow0 + 64) * 128 + aC0];
    rb0 = bValid ? *(const float4*)&X[(size_t)bR0 * N + nb] : z4;
    rb1 = bValid ? *(const float4*)&X[(size_t)(bR0 + 8) * N + nb] : z4;

    for (int kc = 0; kc < 128; kc += 16) {
        // commit prefetched tile to smem
        As[aC0 + 0][aRow0] = ra0.x; As[aC0 + 1][aRow0] = ra0.y;
        As[aC0 + 2][aRow0] = ra0.z; As[aC0 + 3][aRow0] = ra0.w;
        As[aC0 + 0][aRow0 + 64] = ra1.x; As[aC0 + 1][aRow0 + 64] = ra1.y;
        As[aC0 + 2][aRow0 + 64] = ra1.z; As[aC0 + 3][aRow0 + 64] = ra1.w;
        *(float4*)&Bs[bR0][bC0]     = rb0;
        *(float4*)&Bs[bR0 + 8][bC0] = rb1;
        __syncthreads();

        if (kc + 16 < 128) {
            const int kn = kc + 16;
            ra0 = *(const float4*)&F[aRow0 * 128 + kn + aC0];
            ra1 = *(const float4*)&F[(aRow0 + 64) * 128 + kn + aC0];
            rb0 = bValid ? *(const float4*)&X[(size_t)(kn + bR0) * N + nb] : z4;
            rb1 = bValid ? *(const float4*)&X[(size_t)(kn + bR0 + 8) * N + nb] : z4;
        }

#pragma unroll
        for (int k = 0; k < 16; k++) {
            float4 a0 = *(const float4*)&As[k][row0];
            float4 a1 = *(const float4*)&As[k][row0 + 4];
            float4 b0 = *(const float4*)&Bs[k][col0];
            float4 b1 = *(const float4*)&Bs[k][col0 + 4];
            unsigned long long A8[8] = {dup2(a0.x), dup2(a0.y), dup2(a0.z), dup2(a0.w),
                                        dup2(a1.x), dup2(a1.y), dup2(a1.z), dup2(a1.w)};
            unsigned long long B4[4] = {pack2(b0.x, b0.y), pack2(b0.z, b0.w),
                                        pack2(b1.x, b1.y), pack2(b1.z, b1.w)};
#pragma unroll
            for (int i = 0; i < 8; i++)
#pragma unroll
                for (int j = 0; j < 4; j++)
                    ffma2(acc[i][j], A8[i], B4[j]);
        }
        __syncthreads();
    }

    // epilogue: store Y + per-row partial stats for this n-tile
    const bool cValid = (n0 + col0) < N;  // whole 8-col group valid or not (N mult of 64)
#pragma unroll
    for (int i = 0; i < 8; i++) {
        const int o = row0 + i;
        float y[8];
#pragma unroll
        for (int j = 0; j < 4; j++) {
            float2 p = unpack2(acc[i][j]);
            y[2 * j] = p.x; y[2 * j + 1] = p.y;
        }
        if (cValid) {
            *(float4*)&Y[(size_t)o * N + n0 + col0]     = make_float4(y[0], y[1], y[2], y[3]);
            *(float4*)&Y[(size_t)o * N + n0 + col0 + 4] = make_float4(y[4], y[5], y[6], y[7]);
        }
        // invalid columns had zero-filled B -> y == 0, contributes nothing to sums
        float s1 = 0.f, s2 = 0.f;
#pragma unroll
        for (int j = 0; j < 8; j++) { s1 += y[j]; s2 += y[j] * y[j]; }
        // reduce across the 16 threads (same ty) holding this row's columns
#pragma unroll
        for (int d = 8; d >= 1; d >>= 1) {
            s1 += __shfl_xor_sync(0xffffffffu, s1, d);
            s2 += __shfl_xor_sync(0xffffffffu, s2, d);
        }
        if (L < 4 && tx == 0) {
            const size_t pidx = (size_t)c_poff[L] + (size_t)(b * 128 + o) * nT + tile;
            g_psum[pidx] = s1;
            g_psq [pidx] = s2;
        }
    }
}

// ---------------- kernel 2: finalize stats + normalize (levels 0-3) ----------------
__global__ __launch_bounds__(256)
void lg5_norm_kernel(float* __restrict__ out) {
    const int L  = blockIdx.y;        // 0..3
    const int bo = blockIdx.x;        // 0..4095 == b*128 + o
    const int N  = c_N[L];
    const int nT = c_nT[L];

    float* row = out + c_yoff[L] + (size_t)bo * N;
    const float* p1 = g_psum + c_poff[L] + (size_t)bo * nT;
    const float* p2 = g_psq  + c_poff[L] + (size_t)bo * nT;

    float s1 = 0.f, s2 = 0.f;
    for (int i = threadIdx.x; i < nT; i += blockDim.x) { s1 += p1[i]; s2 += p2[i]; }
#pragma unroll
    for (int d = 16; d >= 1; d >>= 1) {
        s1 += __shfl_xor_sync(0xffffffffu, s1, d);
        s2 += __shfl_xor_sync(0xffffffffu, s2, d);
    }
    __shared__ float sh1[8], sh2[8];
    __shared__ float stats[2];
    const int w = threadIdx.x >> 5, lane = threadIdx.x & 31;
    if (lane == 0) { sh1[w] = s1; sh2[w] = s2; }
    __syncthreads();
    if (threadIdx.x == 0) {
        float S1 = 0.f, S2 = 0.f;
#pragma unroll
        for (int i = 0; i < 8; i++) { S1 += sh1[i]; S2 += sh2[i]; }
        const float invN = 1.0f / (float)N;
        const float mean = S1 * invN;
        const float var  = S2 * invN - mean * mean;
        stats[0] = mean;
        stats[1] = rsqrtf(var + EPSN);
    }
    __syncthreads();
    const float mean = stats[0], rstd = stats[1];
    for (int i = threadIdx.x * 4; i < N; i += blockDim.x * 4) {
        float4 v = *(const float4*)&row[i];
        v.x = (v.x - mean) * rstd;
        v.y = (v.y - mean) * rstd;
        v.z = (v.z - mean) * rstd;
        v.w = (v.w - mean) * rstd;
        *(float4*)&row[i] = v;
    }
}

// ---------------- launch ----------------
extern "C" void kernel_launch(void* const* d_in, const int* in_sizes, int n_in,
                              void* d_out, int out_size) {
    // identify inputs by element count (robust to metadata ordering);
    // the five filters (all 524288 elems) are l1fs..l5fs in appearance order.
    const float* xs[5] = {0, 0, 0, 0, 0};
    const float* fs[5] = {0, 0, 0, 0, 0};
    int fc = 0;
    for (int i = 0; i < n_in; i++) {
        const float* p = (const float*)d_in[i];
        switch (in_sizes[i]) {
            case 67108864: xs[0] = p; break;  // x1: 32*128*128*128
            case 16777216: xs[1] = p; break;  // x2: 32*128*64*64
            case 4194304:  xs[2] = p; break;  // x3: 32*128*32*32
            case 1048576:  xs[3] = p; break;  // x4: 32*128*16*16
            case 262144:   xs[4] = p; break;  // x5: 32*128*8*8
            case 524288:   if (fc < 5) fs[fc++] = p; break;  // l{i}fs: 32*128*128
        }
    }
    float* out = (float*)d_out;
    lg5_gemm_kernel<<<5472, 256>>>(xs[0], xs[1], xs[2], xs[3], xs[4],
                                   fs[0], fs[1], fs[2], fs[3], fs[4], out);
    lg5_norm_kernel<<<dim3(4096, 4), 256>>>(out);
}

// round 5
// speedup vs baseline: 1.3527x; 1.3444x over previous
#include <cuda_runtime.h>
#include <cuda_bf16.h>
#include <cstdint>

// Lingunet5Filter — HMMA (mma.sync bf16, fp32-accum) split-GEMM:
//   fp32 emulated as D = Ah*Bh + Ah*Bl + Al*Bh  (2-term bf16 split, al*bl dropped ~2^-16)
//   Y[b](128 x N) = F[b](128x128) @ X[b](128 x N), N in {16384,4096,1024,256,64}, B=32
// + register-resident instance-norm kernels (levels 0-3).

#define EPSN  1e-5f
#define PITCH 136   // bf16 elements per smem row (272 B) -> ldmatrix conflict-free
#define FPITCH 68   // float elements per epilogue row (272 B)

static __device__ __forceinline__ uint32_t smem_u32(const void* p) {
    uint32_t a;
    asm("{ .reg .u64 t; cvta.to.shared.u64 t, %1; cvt.u32.u64 %0, t; }" : "=r"(a) : "l"(p));
    return a;
}
static __device__ __forceinline__ uint32_t pack_bf2(float a, float b) {
    __nv_bfloat162 t = __floats2bfloat162_rn(a, b);
    return *reinterpret_cast<uint32_t*>(&t);
}

#define LDSM4(r, addr)                                                          \
    asm volatile("ldmatrix.sync.aligned.m8n8.x4.shared.b16 {%0,%1,%2,%3}, [%4];" \
                 : "=r"((r)[0]), "=r"((r)[1]), "=r"((r)[2]), "=r"((r)[3])        \
                 : "r"(addr))

#define MMA16816(d, a, b0, b1)                                                  \
    asm volatile("mma.sync.aligned.m16n8k16.row.col.f32.bf16.bf16.f32 "          \
                 "{%0,%1,%2,%3}, {%4,%5,%6,%7}, {%8,%9}, {%0,%1,%2,%3};"         \
                 : "+f"((d)[0]), "+f"((d)[1]), "+f"((d)[2]), "+f"((d)[3])        \
                 : "r"((a)[0]), "r"((a)[1]), "r"((a)[2]), "r"((a)[3]),           \
                   "r"(b0), "r"(b1))

// ---------------- kernel 1: HMMA batched GEMM ----------------
__global__ __launch_bounds__(256, 2)
void lg5_hmma(const float* __restrict__ x0, const float* __restrict__ x1,
              const float* __restrict__ x2, const float* __restrict__ x3,
              const float* __restrict__ x4,
              const float* __restrict__ f0, const float* __restrict__ f1,
              const float* __restrict__ f2, const float* __restrict__ f3,
              const float* __restrict__ f4,
              float* __restrict__ out) {
    extern __shared__ char smem[];
    __nv_bfloat16* AH = (__nv_bfloat16*)smem;                 // 128 x PITCH
    __nv_bfloat16* AL = AH + 128 * PITCH;
    __nv_bfloat16* BH = AL + 128 * PITCH;                     // 64 x PITCH
    __nv_bfloat16* BL = BH + 64 * PITCH;
    float*         T  = (float*)smem;                         // epilogue overlay (128 x FPITCH)

    // ---- level / tile decode (n-tiles of 64; every level is a multiple of 64) ----
    const int bx = blockIdx.x;
    int L, t0;
    if (bx < 8192)       { L = 0; t0 = bx; }
    else if (bx < 10240) { L = 1; t0 = bx - 8192; }
    else if (bx < 10752) { L = 2; t0 = bx - 10240; }
    else if (bx < 10880) { L = 3; t0 = bx - 10752; }
    else                 { L = 4; t0 = bx - 10880; }

    int N, nT;
    long long yoff;
    const float *X, *F;
    if (L == 0)      { N = 16384; nT = 256; yoff = 0LL;        X = x0; F = f0; }
    else if (L == 1) { N = 4096;  nT = 64;  yoff = 67108864LL; X = x1; F = f1; }
    else if (L == 2) { N = 1024;  nT = 16;  yoff = 83886080LL; X = x2; F = f2; }
    else if (L == 3) { N = 256;   nT = 4;   yoff = 88080384LL; X = x3; F = f3; }
    else             { N = 64;    nT = 1;   yoff = 89128960LL; X = x4; F = f4; }

    const int b    = t0 / nT;
    const int tile = t0 - b * nT;
    const int n0   = tile * 64;

    X += (size_t)b * 128 * N;
    F += (size_t)b * 128 * 128;
    float* Y = out + yoff + (size_t)b * 128 * N;

    const int tid = threadIdx.x;

    // ---- load F -> AH/AL (coalesced float4; 16 float4 per thread) ----
#pragma unroll
    for (int i = 0; i < 16; i++) {
        const int e   = (i * 256 + tid) * 4;
        const int row = e >> 7;
        const int k   = e & 127;
        const float4 f = *(const float4*)(F + e);
        const float h0 = __bfloat162float(__float2bfloat16(f.x));
        const float h1 = __bfloat162float(__float2bfloat16(f.y));
        const float h2 = __bfloat162float(__float2bfloat16(f.z));
        const float h3 = __bfloat162float(__float2bfloat16(f.w));
        uint2 hi2, lo2;
        hi2.x = pack_bf2(h0, h1);        hi2.y = pack_bf2(h2, h3);
        lo2.x = pack_bf2(f.x - h0, f.y - h1);
        lo2.y = pack_bf2(f.z - h2, f.w - h3);
        *(uint2*)(AH + row * PITCH + k) = hi2;
        *(uint2*)(AL + row * PITCH + k) = lo2;
    }

    // ---- load X^T tile -> BH/BL (coalesced LDG.32; B[n][k] = X[k][n0+n]) ----
    {
        const int n  = tid & 63;
        const int cb = (tid >> 6) * 32;
        const float* xp = X + (size_t)cb * N + n0 + n;
#pragma unroll
        for (int c = 0; c < 32; c += 2) {
            const float v0 = xp[(size_t)c * N];
            const float v1 = xp[(size_t)(c + 1) * N];
            const float h0 = __bfloat162float(__float2bfloat16(v0));
            const float h1 = __bfloat162float(__float2bfloat16(v1));
            *(uint32_t*)(BH + n * PITCH + cb + c) = pack_bf2(h0, h1);
            *(uint32_t*)(BL + n * PITCH + cb + c) = pack_bf2(v0 - h0, v1 - h1);
        }
    }
    __syncthreads();

    // ---- HMMA mainloop: warp tile 32m x 32n, 3 products, 8 k-steps ----
    const int wid  = tid >> 5;
    const int lane = tid & 31;
    const int wm   = (wid >> 1) * 32;
    const int wn   = (wid & 1) * 32;

    float d[8][4];
#pragma unroll
    for (int i = 0; i < 8; i++)
#pragma unroll
        for (int j = 0; j < 4; j++) d[i][j] = 0.f;

    const int arow = lane & 15;
    const int acol = (lane >> 4) * 8;
    const int brow = (lane & 7) + ((lane >> 4) << 3);
    const int bcol = ((lane >> 3) & 1) * 8;

#pragma unroll
    for (int p = 0; p < 3; p++) {
        const __nv_bfloat16* Ap = (p == 2) ? AL : AH;
        const __nv_bfloat16* Bp = (p == 1) ? BL : BH;
        const uint32_t aB0 = smem_u32(Ap + (wm + arow) * PITCH + acol);
        const uint32_t aB1 = aB0 + 16 * PITCH * 2;
        const uint32_t bB0 = smem_u32(Bp + (wn + brow) * PITCH + bcol);
        const uint32_t bB1 = bB0 + 16 * PITCH * 2;
#pragma unroll
        for (int ks = 0; ks < 8; ks++) {
            const uint32_t ko = ks * 32;  // 16 bf16 = 32 B
            uint32_t a0[4], a1[4], bb0[4], bb1[4];
            LDSM4(a0, aB0 + ko);
            LDSM4(a1, aB1 + ko);
            LDSM4(bb0, bB0 + ko);
            LDSM4(bb1, bB1 + ko);
            MMA16816(d[0], a0, bb0[0], bb0[1]);
            MMA16816(d[1], a0, bb0[2], bb0[3]);
            MMA16816(d[2], a0, bb1[0], bb1[1]);
            MMA16816(d[3], a0, bb1[2], bb1[3]);
            MMA16816(d[4], a1, bb0[0], bb0[1]);
            MMA16816(d[5], a1, bb0[2], bb0[3]);
            MMA16816(d[6], a1, bb1[0], bb1[1]);
            MMA16816(d[7], a1, bb1[2], bb1[3]);
        }
    }
    __syncthreads();   // all warps done reading AH/AL before T overlays them

    // ---- epilogue: d frags -> smem bounce -> coalesced STG ----
#pragma unroll
    for (int mi = 0; mi < 2; mi++)
#pragma unroll
        for (int nj = 0; nj < 4; nj++) {
            const int row = wm + mi * 16 + (lane >> 2);
            const int col = wn + nj * 8 + 2 * (lane & 3);
            const float* dd = d[mi * 4 + nj];
            *(float2*)&T[row * FPITCH + col]       = make_float2(dd[0], dd[1]);
            *(float2*)&T[(row + 8) * FPITCH + col] = make_float2(dd[2], dd[3]);
        }
    __syncthreads();

    const int r0 = tid >> 4;
    const int c0 = (tid & 15) * 4;
#pragma unroll
    for (int i = 0; i < 8; i++) {
        const int row = r0 + i * 16;
        const float4 v = *(const float4*)&T[row * FPITCH + c0];
        *(float4*)&Y[(size_t)row * N + n0 + c0] = v;
    }
}

// ---------------- kernel 2: register-resident instance norm ----------------
template <int ITERS>
__global__ __launch_bounds__(256)
void lg5_norm_k(float* __restrict__ out, size_t yoff, int N) {
    float* row = out + yoff + (size_t)blockIdx.x * N;
    const int tid = threadIdx.x;

    float4 v[ITERS];
    float s1 = 0.f, s2 = 0.f;
#pragma unroll
    for (int i = 0; i < ITERS; i++) {
        const int idx = i * 1024 + tid * 4;
        if (idx < N) {
            v[i] = *(const float4*)(row + idx);
            s1 += v[i].x + v[i].y + v[i].z + v[i].w;
            s2 += v[i].x * v[i].x + v[i].y * v[i].y + v[i].z * v[i].z + v[i].w * v[i].w;
        }
    }
#pragma unroll
    for (int dl = 16; dl >= 1; dl >>= 1) {
        s1 += __shfl_xor_sync(0xffffffffu, s1, dl);
        s2 += __shfl_xor_sync(0xffffffffu, s2, dl);
    }
    __shared__ float a1[8], a2[8], st[2];
    const int w = tid >> 5, lane = tid & 31;
    if (lane == 0) { a1[w] = s1; a2[w] = s2; }
    __syncthreads();
    if (tid == 0) {
        float S1 = 0.f, S2 = 0.f;
#pragma unroll
        for (int i = 0; i < 8; i++) { S1 += a1[i]; S2 += a2[i]; }
        const float invN = 1.0f / (float)N;
        const float mean = S1 * invN;
        const float var  = S2 * invN - mean * mean;
        st[0] = mean;
        st[1] = rsqrtf(var + EPSN);
    }
    __syncthreads();
    const float mean = st[0], rstd = st[1];
#pragma unroll
    for (int i = 0; i < ITERS; i++) {
        const int idx = i * 1024 + tid * 4;
        if (idx < N) {
            float4 t = v[i];
            t.x = (t.x - mean) * rstd;
            t.y = (t.y - mean) * rstd;
            t.z = (t.z - mean) * rstd;
            t.w = (t.w - mean) * rstd;
            *(float4*)(row + idx) = t;
        }
    }
}

// ---------------- launch ----------------
extern "C" void kernel_launch(void* const* d_in, const int* in_sizes, int n_in,
                              void* d_out, int out_size) {
    const float* xs[5] = {0, 0, 0, 0, 0};
    const float* fs[5] = {0, 0, 0, 0, 0};
    int fc = 0;
    for (int i = 0; i < n_in; i++) {
        const float* p = (const float*)d_in[i];
        switch (in_sizes[i]) {
            case 67108864: xs[0] = p; break;
            case 16777216: xs[1] = p; break;
            case 4194304:  xs[2] = p; break;
            case 1048576:  xs[3] = p; break;
            case 262144:   xs[4] = p; break;
            case 524288:   if (fc < 5) fs[fc++] = p; break;
        }
    }
    float* out = (float*)d_out;

    const int smem_bytes = (128 * PITCH + 128 * PITCH + 64 * PITCH + 64 * PITCH) * 2; // 104448
    cudaFuncSetAttribute(lg5_hmma, cudaFuncAttributeMaxDynamicSharedMemorySize, smem_bytes);
    lg5_hmma<<<10912, 256, smem_bytes>>>(xs[0], xs[1], xs[2], xs[3], xs[4],
                                         fs[0], fs[1], fs[2], fs[3], fs[4], out);

    lg5_norm_k<16><<<4096, 256>>>(out, 0,           16384);
    lg5_norm_k<4> <<<4096, 256>>>(out, 67108864ULL, 4096);
    lg5_norm_k<1> <<<4096, 256>>>(out, 83886080ULL, 1024);
    lg5_norm_k<1> <<<4096, 256>>>(out, 88080384ULL, 256);
}

// round 6
// speedup vs baseline: 1.6904x; 1.2497x over previous
#include <cuda_runtime.h>
#include <cuda_fp16.h>
#include <cstdint>

// Lingunet5Filter — HMMA fp16 asymmetric-split GEMM (2 products):
//   A = F split into Ah + Al (fp16 pair, ~22 mantissa bits); B = fp16(X).
//   D = Ah*Bh + Al*Bh  -> error only from B rounding (~2^-12 aggregate).
//   Y[b](128 x N) = F[b](128x128) @ X[b](128 x N), N in {16384,4096,1024,256,64}, B=32
// + register-resident instance-norm kernels (levels 0-3).

#define EPSN  1e-5f
#define PITCH 136   // fp16 elems per smem row (272 B) -> ldmatrix conflict-free
#define FPITCH 132  // float elems per epilogue bounce row

static __device__ __forceinline__ uint32_t smem_u32(const void* p) {
    uint32_t a;
    asm("{ .reg .u64 t; cvta.to.shared.u64 t, %1; cvt.u32.u64 %0, t; }" : "=r"(a) : "l"(p));
    return a;
}
static __device__ __forceinline__ uint32_t pack_h2(float a, float b) {
    __half2 t = __floats2half2_rn(a, b);
    return *reinterpret_cast<uint32_t*>(&t);
}

#define LDSM4(r, addr)                                                          \
    asm volatile("ldmatrix.sync.aligned.m8n8.x4.shared.b16 {%0,%1,%2,%3}, [%4];" \
                 : "=r"((r)[0]), "=r"((r)[1]), "=r"((r)[2]), "=r"((r)[3])        \
                 : "r"(addr))

#define MMA16816(d, a, b0, b1)                                                  \
    asm volatile("mma.sync.aligned.m16n8k16.row.col.f32.f16.f16.f32 "            \
                 "{%0,%1,%2,%3}, {%4,%5,%6,%7}, {%8,%9}, {%0,%1,%2,%3};"         \
                 : "+f"((d)[0]), "+f"((d)[1]), "+f"((d)[2]), "+f"((d)[3])        \
                 : "r"((a)[0]), "r"((a)[1]), "r"((a)[2]), "r"((a)[3]),           \
                   "r"(b0), "r"(b1))

// ---------------- kernel 1: HMMA batched GEMM (CTA tile 128m x 128n, K=128) ----------------
__global__ __launch_bounds__(256, 2)
void lg5_hmma(const float* __restrict__ x0, const float* __restrict__ x1,
              const float* __restrict__ x2, const float* __restrict__ x3,
              const float* __restrict__ x4,
              const float* __restrict__ f0, const float* __restrict__ f1,
              const float* __restrict__ f2, const float* __restrict__ f3,
              const float* __restrict__ f4,
              float* __restrict__ out) {
    extern __shared__ char smem[];
    __half* AH = (__half*)smem;             // 128 x PITCH
    __half* AL = AH + 128 * PITCH;          // 128 x PITCH
    __half* BH = AL + 128 * PITCH;          // 128 x PITCH
    float*  T  = (float*)smem;              // epilogue overlay (128 x FPITCH) over AH/AL

    // ---- level / tile decode (n-tiles of 128) ----
    const int bx = blockIdx.x;
    int L, t0;
    if (bx < 4096)      { L = 0; t0 = bx; }
    else if (bx < 5120) { L = 1; t0 = bx - 4096; }
    else if (bx < 5376) { L = 2; t0 = bx - 5120; }
    else if (bx < 5440) { L = 3; t0 = bx - 5376; }
    else                { L = 4; t0 = bx - 5440; }

    int N, nT;
    long long yoff;
    const float *X, *F;
    if (L == 0)      { N = 16384; nT = 128; yoff = 0LL;        X = x0; F = f0; }
    else if (L == 1) { N = 4096;  nT = 32;  yoff = 67108864LL; X = x1; F = f1; }
    else if (L == 2) { N = 1024;  nT = 8;   yoff = 83886080LL; X = x2; F = f2; }
    else if (L == 3) { N = 256;   nT = 2;   yoff = 88080384LL; X = x3; F = f3; }
    else             { N = 64;    nT = 1;   yoff = 89128960LL; X = x4; F = f4; }

    const int b    = t0 / nT;
    const int tile = t0 - b * nT;
    const int n0   = tile * 128;

    X += (size_t)b * 128 * N;
    F += (size_t)b * 128 * 128;
    float* Y = out + yoff + (size_t)b * 128 * N;

    const int tid = threadIdx.x;

    // ---- load F -> AH/AL (coalesced float4; 16 float4 per thread) ----
#pragma unroll
    for (int i = 0; i < 16; i++) {
        const int e   = (i * 256 + tid) * 4;
        const int row = e >> 7;
        const int k   = e & 127;
        const float4 f = *(const float4*)(F + e);
        const float h0 = __half2float(__float2half_rn(f.x));
        const float h1 = __half2float(__float2half_rn(f.y));
        const float h2 = __half2float(__float2half_rn(f.z));
        const float h3 = __half2float(__float2half_rn(f.w));
        uint2 hi2, lo2;
        hi2.x = pack_h2(h0, h1);
        hi2.y = pack_h2(h2, h3);
        lo2.x = pack_h2(f.x - h0, f.y - h1);
        lo2.y = pack_h2(f.z - h2, f.w - h3);
        *(uint2*)(AH + row * PITCH + k) = hi2;
        *(uint2*)(AL + row * PITCH + k) = lo2;
    }

    // ---- load X^T tile -> BH (coalesced LDG.32; B[n][k] = X[k][n0+n]) ----
    {
        const int n  = tid & 127;          // 128 threads -> 512B coalesced
        const int c0 = (tid >> 7) * 64;    // two K halves
        const bool nv = (n0 + n) < N;      // level-4 tail rows
        const float* xp = X + (size_t)c0 * N + n0 + n;
#pragma unroll
        for (int c = 0; c < 64; c += 2) {
            float v0 = 0.f, v1 = 0.f;
            if (nv) {
                v0 = xp[(size_t)c * N];
                v1 = xp[(size_t)(c + 1) * N];
            }
            *(uint32_t*)(BH + n * PITCH + c0 + c) = pack_h2(v0, v1);
        }
    }
    __syncthreads();

    // ---- HMMA mainloop: warp tile 32m x 64n, 2 products, 8 k-steps ----
    const int wid  = tid >> 5;
    const int lane = tid & 31;
    const int wm   = (wid >> 1) * 32;
    const int wn   = (wid & 1) * 64;

    float d[16][4];
#pragma unroll
    for (int i = 0; i < 16; i++)
#pragma unroll
        for (int j = 0; j < 4; j++) d[i][j] = 0.f;

    const int arow = lane & 15;
    const int acol = (lane >> 4) * 8;
    const int brow = (lane & 7) + ((lane >> 4) << 3);
    const int bcol = ((lane >> 3) & 1) * 8;

    const uint32_t aH0 = smem_u32(AH + (wm + arow) * PITCH + acol);
    const uint32_t aH1 = aH0 + 16 * PITCH * 2;
    const uint32_t aL0 = smem_u32(AL + (wm + arow) * PITCH + acol);
    const uint32_t aL1 = aL0 + 16 * PITCH * 2;
    const uint32_t bB  = smem_u32(BH + (wn + brow) * PITCH + bcol);

#pragma unroll
    for (int ks = 0; ks < 8; ks++) {
        const uint32_t ko = ks * 32;  // 16 halves = 32 B
        uint32_t bb[4][4];
#pragma unroll
        for (int t = 0; t < 4; t++)
            LDSM4(bb[t], bB + t * (16 * PITCH * 2) + ko);

        uint32_t a0[4], a1[4];
        LDSM4(a0, aH0 + ko);
        LDSM4(a1, aH1 + ko);
#pragma unroll
        for (int t = 0; t < 4; t++) {
            MMA16816(d[2 * t + 0], a0, bb[t][0], bb[t][1]);
            MMA16816(d[2 * t + 1], a0, bb[t][2], bb[t][3]);
            MMA16816(d[2 * t + 8], a1, bb[t][0], bb[t][1]);
            MMA16816(d[2 * t + 9], a1, bb[t][2], bb[t][3]);
        }
        LDSM4(a0, aL0 + ko);
        LDSM4(a1, aL1 + ko);
#pragma unroll
        for (int t = 0; t < 4; t++) {
            MMA16816(d[2 * t + 0], a0, bb[t][0], bb[t][1]);
            MMA16816(d[2 * t + 1], a0, bb[t][2], bb[t][3]);
            MMA16816(d[2 * t + 8], a1, bb[t][0], bb[t][1]);
            MMA16816(d[2 * t + 9], a1, bb[t][2], bb[t][3]);
        }
    }
    __syncthreads();   // all warps done reading AH/AL before T overlays them

    // ---- epilogue: d frags -> smem bounce -> coalesced STG ----
    // frag (mi, nj): rows wm + mi*16 + {lane>>2, +8}, cols wn + nj*8 + 2*(lane&3)
#pragma unroll
    for (int mi = 0; mi < 2; mi++)
#pragma unroll
        for (int nj = 0; nj < 8; nj++) {
            const int row = wm + mi * 16 + (lane >> 2);
            const int col = wn + nj * 8 + 2 * (lane & 3);
            const float* dd = d[mi * 8 + nj];
            *(float2*)&T[row * FPITCH + col]       = make_float2(dd[0], dd[1]);
            *(float2*)&T[(row + 8) * FPITCH + col] = make_float2(dd[2], dd[3]);
        }
    __syncthreads();

    const int r0 = tid >> 5;            // 0..7
    const int c0 = (tid & 31) * 4;      // 0..124
    const bool sv = (L < 4) || (c0 < 64);   // level-4 tail columns (n0 == 0 there)
#pragma unroll
    for (int i = 0; i < 16; i++) {
        const int row = r0 + i * 8;
        const float4 v = *(const float4*)&T[row * FPITCH + c0];
        if (sv) *(float4*)&Y[(size_t)row * N + n0 + c0] = v;
    }
}

// ---------------- kernel 2: register-resident instance norm ----------------
template <int ITERS>
__global__ __launch_bounds__(256)
void lg5_norm_k(float* __restrict__ out, size_t yoff, int N) {
    float* row = out + yoff + (size_t)blockIdx.x * N;
    const int tid = threadIdx.x;

    float4 v[ITERS];
    float s1 = 0.f, s2 = 0.f;
#pragma unroll
    for (int i = 0; i < ITERS; i++) {
        const int idx = i * 1024 + tid * 4;
        if (idx < N) {
            v[i] = *(const float4*)(row + idx);
            s1 += v[i].x + v[i].y + v[i].z + v[i].w;
            s2 += v[i].x * v[i].x + v[i].y * v[i].y + v[i].z * v[i].z + v[i].w * v[i].w;
        }
    }
#pragma unroll
    for (int dl = 16; dl >= 1; dl >>= 1) {
        s1 += __shfl_xor_sync(0xffffffffu, s1, dl);
        s2 += __shfl_xor_sync(0xffffffffu, s2, dl);
    }
    __shared__ float a1[8], a2[8], st[2];
    const int w = tid >> 5, lane = tid & 31;
    if (lane == 0) { a1[w] = s1; a2[w] = s2; }
    __syncthreads();
    if (tid == 0) {
        float S1 = 0.f, S2 = 0.f;
#pragma unroll
        for (int i = 0; i < 8; i++) { S1 += a1[i]; S2 += a2[i]; }
        const float invN = 1.0f / (float)N;
        const float mean = S1 * invN;
        const float var  = S2 * invN - mean * mean;
        st[0] = mean;
        st[1] = rsqrtf(var + EPSN);
    }
    __syncthreads();
    const float mean = st[0], rstd = st[1];
#pragma unroll
    for (int i = 0; i < ITERS; i++) {
        const int idx = i * 1024 + tid * 4;
        if (idx < N) {
            float4 t = v[i];
            t.x = (t.x - mean) * rstd;
            t.y = (t.y - mean) * rstd;
            t.z = (t.z - mean) * rstd;
            t.w = (t.w - mean) * rstd;
            *(float4*)(row + idx) = t;
        }
    }
}

// ---------------- launch ----------------
extern "C" void kernel_launch(void* const* d_in, const int* in_sizes, int n_in,
                              void* d_out, int out_size) {
    const float* xs[5] = {0, 0, 0, 0, 0};
    const float* fs[5] = {0, 0, 0, 0, 0};
    int fc = 0;
    for (int i = 0; i < n_in; i++) {
        const float* p = (const float*)d_in[i];
        switch (in_sizes[i]) {
            case 67108864: xs[0] = p; break;
            case 16777216: xs[1] = p; break;
            case 4194304:  xs[2] = p; break;
            case 1048576:  xs[3] = p; break;
            case 262144:   xs[4] = p; break;
            case 524288:   if (fc < 5) fs[fc++] = p; break;
        }
    }
    float* out = (float*)d_out;

    const int smem_bytes = 3 * 128 * PITCH * 2;   // AH + AL + BH = 104448 B
    cudaFuncSetAttribute(lg5_hmma, cudaFuncAttributeMaxDynamicSharedMemorySize, smem_bytes);
    lg5_hmma<<<5472, 256, smem_bytes>>>(xs[0], xs[1], xs[2], xs[3], xs[4],
                                        fs[0], fs[1], fs[2], fs[3], fs[4], out);

    lg5_norm_k<16><<<4096, 256>>>(out, 0,           16384);
    lg5_norm_k<4> <<<4096, 256>>>(out, 67108864ULL, 4096);
    lg5_norm_k<1> <<<4096, 256>>>(out, 83886080ULL, 1024);
    lg5_norm_k<1> <<<4096, 256>>>(out, 88080384ULL, 256);
}